// round 6
// baseline (speedup 1.0000x reference)
#include <cuda_runtime.h>
#include <cuda_fp16.h>

#define EMBED 128
#define ATTR 25
#define REM 28
#define NLEVEL 50
#define NCOMB 240         // 2*2*3*20 combined type/feature/exchange/pair rows
#define NROWS (NLEVEL + NCOMB)   // 290

// fp16 table: 290 rows * 128 halves = 74240 B
#define TBL_HALVES (NROWS * EMBED)
#define TBL_BYTES  (TBL_HALVES * 2)          // 74240

// Table-build kernel smem: W^T (16384 f32) + 77 temp rows (9856 f32)
#define TK_TEMP 16384
#define TK_SMEM_BYTES ((TK_TEMP + 77 * EMBED) * 4)   // 104960

__device__ __half g_Th[TBL_HALVES];

// Single block: project all tables through W, fold b into pair rows,
// combine type/feature/exchange/pair into 240 rows, emit fp16.
__global__ void __launch_bounds__(1024, 1)
table_kernel(const float* __restrict__ level_tab,
             const float* __restrict__ type_tab,
             const float* __restrict__ feature_tab,
             const float* __restrict__ exchange_tab,
             const float* __restrict__ pair_tab,
             const float* __restrict__ W,
             const float* __restrict__ b)
{
    extern __shared__ float sm[];
    float* sWt  = sm;             // sWt[k*128+e] = W[e][k] (conflict-free dot reads)
    float* sTmp = sm + TK_TEMP;   // 77 projected rows, fp32

    for (int i = threadIdx.x; i < EMBED * EMBED; i += 1024) {
        int e = i >> 7, k = i & 127;
        sWt[k * EMBED + e] = W[i];
    }
    __syncthreads();

    // 77 projected rows: 0-49 level, 50-51 type, 52-53 feature, 54-56 exchange, 57-76 pair(+b)
    for (int i = threadIdx.x; i < 77 * EMBED; i += 1024) {
        int r = i >> 7, e = i & 127;
        const float* tab; int off, dim; float s = 0.0f;
        if (r < 50)      { tab = level_tab    + r * ATTR;        off = 0;   dim = ATTR; }
        else if (r < 52) { tab = type_tab     + (r - 50) * ATTR; off = 25;  dim = ATTR; }
        else if (r < 54) { tab = feature_tab  + (r - 52) * ATTR; off = 50;  dim = ATTR; }
        else if (r < 57) { tab = exchange_tab + (r - 54) * ATTR; off = 75;  dim = ATTR; }
        else             { tab = pair_tab     + (r - 57) * REM;  off = 100; dim = REM; s = b[e]; }
        #pragma unroll 5
        for (int k = 0; k < dim; k++)
            s += tab[k] * sWt[(off + k) * EMBED + e];
        sTmp[r * EMBED + e] = s;
    }
    __syncthreads();

    // Emit fp16: rows 0..49 = level; rows 50..289 = combined c=((t*2+f)*3+x)*20+p
    for (int i = threadIdx.x; i < NLEVEL * EMBED; i += 1024)
        g_Th[i] = __float2half_rn(sTmp[i]);
    for (int i = threadIdx.x; i < NCOMB * EMBED; i += 1024) {
        int c = i >> 7, e = i & 127;
        int p = c % 20, x = (c / 20) % 3, f = (c / 60) % 2, t = c / 120;
        float s = sTmp[(50 + t) * EMBED + e]
                + sTmp[(52 + f) * EMBED + e]
                + sTmp[(54 + x) * EMBED + e]
                + sTmp[(57 + p) * EMBED + e];    // b folded into pair rows
        g_Th[(NLEVEL + c) * EMBED + i % EMBED] = __float2half_rn(s);
    }
}

// Streaming kernel: 3 blocks x 512 threads per SM (48 warps), fp16 tables in smem.
// Warp per row, 4 rows/iter; lane owns outputs e = lane*4 .. lane*4+3.
__global__ void __launch_bounds__(512, 3)
gather_sum_kernel(const int* __restrict__ level_idx,
                  const int* __restrict__ type_idx,
                  const int* __restrict__ feature_idx,
                  const int* __restrict__ exchange_idx,
                  const int* __restrict__ pair_idx,
                  float4* __restrict__ out, int n)
{
    extern __shared__ uint2 sT2[];   // 290 rows * 32 uint2 (8 B = 4 halves per lane)
    {
        const float4* src = reinterpret_cast<const float4*>(g_Th);
        float4* dst = reinterpret_cast<float4*>(sT2);
        for (int i = threadIdx.x; i < TBL_BYTES / 16; i += 512) dst[i] = src[i];
    }
    __syncthreads();

    const int lane   = threadIdx.x & 31;
    const int warp   = (blockIdx.x * 512 + threadIdx.x) >> 5;
    const int nwarps = (gridDim.x * 512) >> 5;

    int r = warp * 4;
    const int stride = nwarps * 4;

    for (; r + 3 < n; r += stride) {
        int4 L = *reinterpret_cast<const int4*>(level_idx + r);
        int4 T = *reinterpret_cast<const int4*>(type_idx + r);
        int4 F = *reinterpret_cast<const int4*>(feature_idx + r);
        int4 X = *reinterpret_cast<const int4*>(exchange_idx + r);
        int4 P = *reinterpret_cast<const int4*>(pair_idx + r);

        int l[4] = {L.x, L.y, L.z, L.w};
        int t[4] = {T.x, T.y, T.z, T.w};
        int f[4] = {F.x, F.y, F.z, F.w};
        int x[4] = {X.x, X.y, X.z, X.w};
        int p[4] = {P.x, P.y, P.z, P.w};

        #pragma unroll
        for (int k = 0; k < 4; k++) {
            int c = ((t[k] * 2 + f[k]) * 3 + x[k]) * 20 + p[k];
            uint2 A = sT2[l[k] * 32 + lane];
            uint2 Q = sT2[(NLEVEL + c) * 32 + lane];
            const __half2* ah = reinterpret_cast<const __half2*>(&A);
            const __half2* qh = reinterpret_cast<const __half2*>(&Q);
            float2 a0 = __half22float2(ah[0]);
            float2 a1 = __half22float2(ah[1]);
            float2 q0 = __half22float2(qh[0]);
            float2 q1 = __half22float2(qh[1]);
            float4 s;
            s.x = a0.x + q0.x;
            s.y = a0.y + q0.y;
            s.z = a1.x + q1.x;
            s.w = a1.y + q1.y;
            __stcs(out + (size_t)(r + k) * 32 + lane, s);
        }
    }
    for (; r < n; r++) {   // tail
        int c = ((type_idx[r] * 2 + feature_idx[r]) * 3 + exchange_idx[r]) * 20 + pair_idx[r];
        uint2 A = sT2[level_idx[r] * 32 + lane];
        uint2 Q = sT2[(NLEVEL + c) * 32 + lane];
        const __half2* ah = reinterpret_cast<const __half2*>(&A);
        const __half2* qh = reinterpret_cast<const __half2*>(&Q);
        float2 a0 = __half22float2(ah[0]);
        float2 a1 = __half22float2(ah[1]);
        float2 q0 = __half22float2(qh[0]);
        float2 q1 = __half22float2(qh[1]);
        float4 s;
        s.x = a0.x + q0.x;
        s.y = a0.y + q0.y;
        s.z = a1.x + q1.x;
        s.w = a1.y + q1.y;
        out[(size_t)r * 32 + lane] = s;
    }
}

extern "C" void kernel_launch(void* const* d_in, const int* in_sizes, int n_in,
                              void* d_out, int out_size) {
    const float* level_tab    = (const float*)d_in[0];
    const float* type_tab     = (const float*)d_in[1];
    const float* feature_tab  = (const float*)d_in[2];
    const float* exchange_tab = (const float*)d_in[3];
    const float* pair_tab     = (const float*)d_in[4];
    const float* W            = (const float*)d_in[5];
    const float* b            = (const float*)d_in[6];
    const int* level_idx      = (const int*)d_in[7];
    const int* type_idx       = (const int*)d_in[8];
    const int* feature_idx    = (const int*)d_in[9];
    const int* exchange_idx   = (const int*)d_in[10];
    const int* pair_idx       = (const int*)d_in[11];

    int n = in_sizes[7];   // N rows

    int sm_count = 148;
    cudaDeviceGetAttribute(&sm_count, cudaDevAttrMultiProcessorCount, 0);

    cudaFuncSetAttribute(table_kernel,
                         cudaFuncAttributeMaxDynamicSharedMemorySize, TK_SMEM_BYTES);
    cudaFuncSetAttribute(gather_sum_kernel,
                         cudaFuncAttributeMaxDynamicSharedMemorySize, TBL_BYTES);

    table_kernel<<<1, 1024, TK_SMEM_BYTES>>>(level_tab, type_tab, feature_tab,
                                             exchange_tab, pair_tab, W, b);

    // 3 blocks/SM x 512 threads = 48 warps/SM, one resident wave
    gather_sum_kernel<<<3 * sm_count, 512, TBL_BYTES>>>(
        level_idx, type_idx, feature_idx, exchange_idx, pair_idx,
        (float4*)d_out, n);
}

// round 7
// speedup vs baseline: 1.0953x; 1.0953x over previous
#include <cuda_runtime.h>
#include <cuda_fp16.h>

#define EMBED 128
#define ATTR 25
#define REM 28
#define NLEVEL 50
#define NCOMB 240                    // 2*2*3*20
#define NFULL (NLEVEL * NCOMB)       // 12000 full-product rows

// Base projected tables (fp32, exact)
__device__ float g_Lrow[NLEVEL * EMBED];
__device__ float g_Crow[NCOMB * EMBED];
// Full product table, fp16: 12000 * 128 * 2 B = 3 MB (L2-resident)
__device__ __half g_Full[NFULL * EMBED];

// ---- Kernel A: 290 blocks, one projected row each. ~2-3us, parallel.
__global__ void __launch_bounds__(128)
base_kernel(const float* __restrict__ level_tab,
            const float* __restrict__ type_tab,
            const float* __restrict__ feature_tab,
            const float* __restrict__ exchange_tab,
            const float* __restrict__ pair_tab,
            const float* __restrict__ W,
            const float* __restrict__ b)
{
    int r = blockIdx.x;          // 0..289
    int e = threadIdx.x;         // 0..127
    const float* wrow = W + e * EMBED;

    if (r < NLEVEL) {
        const float* lt = level_tab + r * ATTR;
        float s = 0.0f;
        #pragma unroll
        for (int k = 0; k < ATTR; k++) s += lt[k] * wrow[k];
        g_Lrow[r * EMBED + e] = s;
    } else {
        int c = r - NLEVEL;
        int p = c % 20, x = (c / 20) % 3, f = (c / 60) % 2, t = c / 120;
        const float* tt = type_tab     + t * ATTR;
        const float* ft = feature_tab  + f * ATTR;
        const float* xt = exchange_tab + x * ATTR;
        const float* pt = pair_tab     + p * REM;
        float s = b[e];
        #pragma unroll
        for (int k = 0; k < ATTR; k++)
            s += tt[k] * wrow[25 + k] + ft[k] * wrow[50 + k] + xt[k] * wrow[75 + k];
        #pragma unroll
        for (int k = 0; k < REM; k++)
            s += pt[k] * wrow[100 + k];
        g_Crow[c * EMBED + e] = s;
    }
}

// ---- Kernel B: expand to 12000-row fp16 full-product table (fp32 sum, one fp16 round).
__global__ void __launch_bounds__(256)
expand_kernel()
{
    // one __half2 (2 elements) per work item: NFULL * 64 items
    const int total = NFULL * (EMBED / 2);
    __half2* full2 = reinterpret_cast<__half2*>(g_Full);
    for (int i = blockIdx.x * 256 + threadIdx.x; i < total; i += gridDim.x * 256) {
        int row = i >> 6;          // / 64
        int pos = (i & 63) << 1;   // element offset (even)
        int l = row / NCOMB;
        int c = row - l * NCOMB;
        float s0 = g_Lrow[l * EMBED + pos]     + g_Crow[c * EMBED + pos];
        float s1 = g_Lrow[l * EMBED + pos + 1] + g_Crow[c * EMBED + pos + 1];
        full2[i] = __floats2half2_rn(s0, s1);
    }
}

// ---- Kernel C: pure streaming gather. No smem. Warp per row, 8 rows/iter.
// Lane owns 4 halves (one uint2) of the row -> one float4 out.
__global__ void __launch_bounds__(256, 6)
gather_kernel(const int* __restrict__ level_idx,
              const int* __restrict__ type_idx,
              const int* __restrict__ feature_idx,
              const int* __restrict__ exchange_idx,
              const int* __restrict__ pair_idx,
              float4* __restrict__ out, int n)
{
    const uint2* full2 = reinterpret_cast<const uint2*>(g_Full);
    const int lane   = threadIdx.x & 31;
    const int warp   = (blockIdx.x * 256 + threadIdx.x) >> 5;
    const int nwarps = (gridDim.x * 256) >> 5;

    int r = warp * 8;
    const int stride = nwarps * 8;

    for (; r + 7 < n; r += stride) {
        int4 L0 = *reinterpret_cast<const int4*>(level_idx + r);
        int4 L1 = *reinterpret_cast<const int4*>(level_idx + r + 4);
        int4 T0 = *reinterpret_cast<const int4*>(type_idx + r);
        int4 T1 = *reinterpret_cast<const int4*>(type_idx + r + 4);
        int4 F0 = *reinterpret_cast<const int4*>(feature_idx + r);
        int4 F1 = *reinterpret_cast<const int4*>(feature_idx + r + 4);
        int4 X0 = *reinterpret_cast<const int4*>(exchange_idx + r);
        int4 X1 = *reinterpret_cast<const int4*>(exchange_idx + r + 4);
        int4 P0 = *reinterpret_cast<const int4*>(pair_idx + r);
        int4 P1 = *reinterpret_cast<const int4*>(pair_idx + r + 4);

        int l[8] = {L0.x, L0.y, L0.z, L0.w, L1.x, L1.y, L1.z, L1.w};
        int t[8] = {T0.x, T0.y, T0.z, T0.w, T1.x, T1.y, T1.z, T1.w};
        int f[8] = {F0.x, F0.y, F0.z, F0.w, F1.x, F1.y, F1.z, F1.w};
        int x[8] = {X0.x, X0.y, X0.z, X0.w, X1.x, X1.y, X1.z, X1.w};
        int p[8] = {P0.x, P0.y, P0.z, P0.w, P1.x, P1.y, P1.z, P1.w};

        uint2 hv[8];
        #pragma unroll
        for (int k = 0; k < 8; k++) {
            int row = l[k] * NCOMB + ((t[k] * 2 + f[k]) * 3 + x[k]) * 20 + p[k];
            hv[k] = __ldg(&full2[row * 32 + lane]);
        }
        #pragma unroll
        for (int k = 0; k < 8; k++) {
            const __half2* hp = reinterpret_cast<const __half2*>(&hv[k]);
            float2 f0 = __half22float2(hp[0]);
            float2 f1 = __half22float2(hp[1]);
            float4 s;
            s.x = f0.x; s.y = f0.y; s.z = f1.x; s.w = f1.y;
            __stcs(out + (size_t)(r + k) * 32 + lane, s);
        }
    }
    for (; r < n; r++) {   // tail
        int row = level_idx[r] * NCOMB
                + ((type_idx[r] * 2 + feature_idx[r]) * 3 + exchange_idx[r]) * 20
                + pair_idx[r];
        uint2 hv = __ldg(&full2[row * 32 + lane]);
        const __half2* hp = reinterpret_cast<const __half2*>(&hv);
        float2 f0 = __half22float2(hp[0]);
        float2 f1 = __half22float2(hp[1]);
        float4 s;
        s.x = f0.x; s.y = f0.y; s.z = f1.x; s.w = f1.y;
        out[(size_t)r * 32 + lane] = s;
    }
}

extern "C" void kernel_launch(void* const* d_in, const int* in_sizes, int n_in,
                              void* d_out, int out_size) {
    const float* level_tab    = (const float*)d_in[0];
    const float* type_tab     = (const float*)d_in[1];
    const float* feature_tab  = (const float*)d_in[2];
    const float* exchange_tab = (const float*)d_in[3];
    const float* pair_tab     = (const float*)d_in[4];
    const float* W            = (const float*)d_in[5];
    const float* b            = (const float*)d_in[6];
    const int* level_idx      = (const int*)d_in[7];
    const int* type_idx       = (const int*)d_in[8];
    const int* feature_idx    = (const int*)d_in[9];
    const int* exchange_idx   = (const int*)d_in[10];
    const int* pair_idx       = (const int*)d_in[11];

    int n = in_sizes[7];   // N rows

    int sm_count = 148;
    cudaDeviceGetAttribute(&sm_count, cudaDevAttrMultiProcessorCount, 0);

    base_kernel<<<NLEVEL + NCOMB, 128>>>(level_tab, type_tab, feature_tab,
                                         exchange_tab, pair_tab, W, b);
    expand_kernel<<<4 * sm_count, 256>>>();

    // 6 blocks/SM x 256 threads = 48 warps/SM, no smem
    gather_kernel<<<6 * sm_count, 256>>>(level_idx, type_idx, feature_idx,
                                         exchange_idx, pair_idx,
                                         (float4*)d_out, n);
}

// round 8
// speedup vs baseline: 1.1679x; 1.0663x over previous
#include <cuda_runtime.h>
#include <cuda_fp16.h>

#define EMBED 128
#define ATTR 25
#define REM 28
#define NLEVEL 50
#define NCOMB 240                    // 2*2*3*20
#define NFULL (NLEVEL * NCOMB)       // 12000 full-product rows

#define WPAD 129                     // smem row pitch (floats) -> conflict-free dot reads
#define BASE_SMEM_BYTES (EMBED * WPAD * 4)   // 66048

// Base projected tables (fp32, exact)
__device__ float g_Lrow[NLEVEL * EMBED];
__device__ float g_Crow[NCOMB * EMBED];
// Full product table, fp16: 12000 * 128 * 2 B = 3 MB (L2-resident)
__device__ __half g_Full[NFULL * EMBED];

// ---- Kernel A: 290 blocks, one projected row each.
// W staged in smem via coalesced float4 loads; padded pitch kills bank conflicts.
__global__ void __launch_bounds__(128)
base_kernel(const float* __restrict__ level_tab,
            const float* __restrict__ type_tab,
            const float* __restrict__ feature_tab,
            const float* __restrict__ exchange_tab,
            const float* __restrict__ pair_tab,
            const float* __restrict__ W,
            const float* __restrict__ b)
{
    extern __shared__ float sW[];    // sW[e*WPAD + k] = W[e][k]
    int tid = threadIdx.x;

    // Coalesced load: 16384 floats as 4096 float4, 128 threads -> 32 each.
    {
        const float4* W4 = reinterpret_cast<const float4*>(W);
        for (int i = tid; i < EMBED * EMBED / 4; i += 128) {
            float4 v = W4[i];
            int e = i >> 5;           // /32 float4 per row
            int k = (i & 31) << 2;
            float* dst = sW + e * WPAD + k;
            dst[0] = v.x; dst[1] = v.y; dst[2] = v.z; dst[3] = v.w;
        }
    }
    __syncthreads();

    int r = blockIdx.x;          // 0..289
    int e = tid;                 // 0..127  (dot reads sW[e*WPAD+k]: lanes span e -> no conflicts)
    const float* we = sW + e * WPAD;

    if (r < NLEVEL) {
        const float* lt = level_tab + r * ATTR;
        float s0 = 0.f, s1 = 0.f, s2 = 0.f, s3 = 0.f;
        #pragma unroll
        for (int k = 0; k < 24; k += 4) {
            s0 += lt[k]     * we[k];
            s1 += lt[k + 1] * we[k + 1];
            s2 += lt[k + 2] * we[k + 2];
            s3 += lt[k + 3] * we[k + 3];
        }
        s0 += lt[24] * we[24];
        g_Lrow[r * EMBED + e] = (s0 + s1) + (s2 + s3);
    } else {
        int c = r - NLEVEL;
        int p = c % 20, x = (c / 20) % 3, f = (c / 60) % 2, t = c / 120;
        const float* tt = type_tab     + t * ATTR;
        const float* ft = feature_tab  + f * ATTR;
        const float* xt = exchange_tab + x * ATTR;
        const float* pt = pair_tab     + p * REM;
        float s0 = b[e], s1 = 0.f, s2 = 0.f, s3 = 0.f;
        #pragma unroll
        for (int k = 0; k < ATTR; k++) {
            s0 += tt[k] * we[25 + k];
            s1 += ft[k] * we[50 + k];
            s2 += xt[k] * we[75 + k];
        }
        #pragma unroll
        for (int k = 0; k < REM; k++)
            s3 += pt[k] * we[100 + k];
        g_Crow[c * EMBED + e] = (s0 + s1) + (s2 + s3);
    }
}

// ---- Kernel B: expand to 12000-row fp16 full-product table (fp32 sum, one fp16 round).
__global__ void __launch_bounds__(256)
expand_kernel()
{
    const int total = NFULL * (EMBED / 2);
    __half2* full2 = reinterpret_cast<__half2*>(g_Full);
    for (int i = blockIdx.x * 256 + threadIdx.x; i < total; i += gridDim.x * 256) {
        int row = i >> 6;          // / 64
        int pos = (i & 63) << 1;
        int l = row / NCOMB;
        int c = row - l * NCOMB;
        float s0 = g_Lrow[l * EMBED + pos]     + g_Crow[c * EMBED + pos];
        float s1 = g_Lrow[l * EMBED + pos + 1] + g_Crow[c * EMBED + pos + 1];
        full2[i] = __floats2half2_rn(s0, s1);
    }
}

// ---- Kernel C: pure streaming gather (unchanged from R7 — at DRAM-write floor).
__global__ void __launch_bounds__(256, 6)
gather_kernel(const int* __restrict__ level_idx,
              const int* __restrict__ type_idx,
              const int* __restrict__ feature_idx,
              const int* __restrict__ exchange_idx,
              const int* __restrict__ pair_idx,
              float4* __restrict__ out, int n)
{
    const uint2* full2 = reinterpret_cast<const uint2*>(g_Full);
    const int lane   = threadIdx.x & 31;
    const int warp   = (blockIdx.x * 256 + threadIdx.x) >> 5;
    const int nwarps = (gridDim.x * 256) >> 5;

    int r = warp * 8;
    const int stride = nwarps * 8;

    for (; r + 7 < n; r += stride) {
        int4 L0 = *reinterpret_cast<const int4*>(level_idx + r);
        int4 L1 = *reinterpret_cast<const int4*>(level_idx + r + 4);
        int4 T0 = *reinterpret_cast<const int4*>(type_idx + r);
        int4 T1 = *reinterpret_cast<const int4*>(type_idx + r + 4);
        int4 F0 = *reinterpret_cast<const int4*>(feature_idx + r);
        int4 F1 = *reinterpret_cast<const int4*>(feature_idx + r + 4);
        int4 X0 = *reinterpret_cast<const int4*>(exchange_idx + r);
        int4 X1 = *reinterpret_cast<const int4*>(exchange_idx + r + 4);
        int4 P0 = *reinterpret_cast<const int4*>(pair_idx + r);
        int4 P1 = *reinterpret_cast<const int4*>(pair_idx + r + 4);

        int l[8] = {L0.x, L0.y, L0.z, L0.w, L1.x, L1.y, L1.z, L1.w};
        int t[8] = {T0.x, T0.y, T0.z, T0.w, T1.x, T1.y, T1.z, T1.w};
        int f[8] = {F0.x, F0.y, F0.z, F0.w, F1.x, F1.y, F1.z, F1.w};
        int x[8] = {X0.x, X0.y, X0.z, X0.w, X1.x, X1.y, X1.z, X1.w};
        int p[8] = {P0.x, P0.y, P0.z, P0.w, P1.x, P1.y, P1.z, P1.w};

        uint2 hv[8];
        #pragma unroll
        for (int k = 0; k < 8; k++) {
            int row = l[k] * NCOMB + ((t[k] * 2 + f[k]) * 3 + x[k]) * 20 + p[k];
            hv[k] = __ldg(&full2[row * 32 + lane]);
        }
        #pragma unroll
        for (int k = 0; k < 8; k++) {
            const __half2* hp = reinterpret_cast<const __half2*>(&hv[k]);
            float2 f0 = __half22float2(hp[0]);
            float2 f1 = __half22float2(hp[1]);
            float4 s;
            s.x = f0.x; s.y = f0.y; s.z = f1.x; s.w = f1.y;
            __stcs(out + (size_t)(r + k) * 32 + lane, s);
        }
    }
    for (; r < n; r++) {   // tail
        int row = level_idx[r] * NCOMB
                + ((type_idx[r] * 2 + feature_idx[r]) * 3 + exchange_idx[r]) * 20
                + pair_idx[r];
        uint2 hv = __ldg(&full2[row * 32 + lane]);
        const __half2* hp = reinterpret_cast<const __half2*>(&hv);
        float2 f0 = __half22float2(hp[0]);
        float2 f1 = __half22float2(hp[1]);
        float4 s;
        s.x = f0.x; s.y = f0.y; s.z = f1.x; s.w = f1.y;
        out[(size_t)r * 32 + lane] = s;
    }
}

extern "C" void kernel_launch(void* const* d_in, const int* in_sizes, int n_in,
                              void* d_out, int out_size) {
    const float* level_tab    = (const float*)d_in[0];
    const float* type_tab     = (const float*)d_in[1];
    const float* feature_tab  = (const float*)d_in[2];
    const float* exchange_tab = (const float*)d_in[3];
    const float* pair_tab     = (const float*)d_in[4];
    const float* W            = (const float*)d_in[5];
    const float* b            = (const float*)d_in[6];
    const int* level_idx      = (const int*)d_in[7];
    const int* type_idx       = (const int*)d_in[8];
    const int* feature_idx    = (const int*)d_in[9];
    const int* exchange_idx   = (const int*)d_in[10];
    const int* pair_idx       = (const int*)d_in[11];

    int n = in_sizes[7];   // N rows

    int sm_count = 148;
    cudaDeviceGetAttribute(&sm_count, cudaDevAttrMultiProcessorCount, 0);

    cudaFuncSetAttribute(base_kernel,
                         cudaFuncAttributeMaxDynamicSharedMemorySize, BASE_SMEM_BYTES);

    base_kernel<<<NLEVEL + NCOMB, 128, BASE_SMEM_BYTES>>>(
        level_tab, type_tab, feature_tab, exchange_tab, pair_tab, W, b);
    expand_kernel<<<4 * sm_count, 256>>>();

    // 6 blocks/SM x 256 threads = 48 warps/SM, no smem
    gather_kernel<<<6 * sm_count, 256>>>(level_idx, type_idx, feature_idx,
                                         exchange_idx, pair_idx,
                                         (float4*)d_out, n);
}